// round 2
// baseline (speedup 1.0000x reference)
#include <cuda_runtime.h>
#include <cuda_bf16.h>
#include <cstdint>

// Problem constants
#define BB 4
#define CC 256
#define CLAT 32
#define NN 4096

// Scratch (device globals -- no allocation allowed)
__device__ float g_Q[BB * NN * CLAT];              // [b][n][32] tf32-rounded
__device__ float g_K[BB * NN * CLAT];              // [b][n][32] tf32-rounded
__device__ __nv_bfloat16 g_Vt[BB * CLAT * NN];     // [b][c][n] bf16
__device__ float g_agg[BB * NN * CLAT];            // [b][n][32] fp32

// ---------------- helpers ----------------
__device__ __forceinline__ uint32_t sa(const void* p) {
    return (uint32_t)__cvta_generic_to_shared(p);
}
__device__ __forceinline__ void cp16(uint32_t s, const void* g) {
    asm volatile("cp.async.cg.shared.global [%0],[%1],16;\n" :: "r"(s), "l"(g));
}
__device__ __forceinline__ void cpc() { asm volatile("cp.async.commit_group;\n"); }
template <int W> __device__ __forceinline__ void cpw() {
    asm volatile("cp.async.wait_group %0;\n" :: "n"(W));
}
__device__ __forceinline__ float ex2f(float x) {
    float y; asm("ex2.approx.f32 %0,%1;" : "=f"(y) : "f"(x)); return y;
}
__device__ __forceinline__ float tf32r(float x) {
    uint32_t u; asm("cvt.rna.tf32.f32 %0,%1;" : "=r"(u) : "f"(x));
    return __uint_as_float(u);
}
// pack two f32 -> bf16x2 (lo in low half, hi in high half)
__device__ __forceinline__ uint32_t pbf2(float lo, float hi) {
    uint32_t r; asm("cvt.rn.bf16x2.f32 %0,%1,%2;" : "=r"(r) : "f"(hi), "f"(lo));
    return r;
}
__device__ __forceinline__ void mma_tf32(float d[4], const uint32_t a[4],
                                         uint32_t b0, uint32_t b1) {
    asm volatile(
        "mma.sync.aligned.m16n8k8.row.col.f32.tf32.tf32.f32 "
        "{%0,%1,%2,%3},{%4,%5,%6,%7},{%8,%9},{%0,%1,%2,%3};\n"
        : "+f"(d[0]), "+f"(d[1]), "+f"(d[2]), "+f"(d[3])
        : "r"(a[0]), "r"(a[1]), "r"(a[2]), "r"(a[3]), "r"(b0), "r"(b1));
}
__device__ __forceinline__ void mma_bf16(float d[4], const uint32_t a[4],
                                         uint32_t b0, uint32_t b1) {
    asm volatile(
        "mma.sync.aligned.m16n8k16.row.col.f32.bf16.bf16.f32 "
        "{%0,%1,%2,%3},{%4,%5,%6,%7},{%8,%9},{%0,%1,%2,%3};\n"
        : "+f"(d[0]), "+f"(d[1]), "+f"(d[2]), "+f"(d[3])
        : "r"(a[0]), "r"(a[1]), "r"(a[2]), "r"(a[3]), "r"(b0), "r"(b1));
}

// ============================================================================
// Kernel 1: QKV projection  out{1,2,3}[b][n][o] = ReLU(bn(W x))
// Tile: 96 outputs x 64 n per block, 256 threads, c-chunks of 32.
// ============================================================================
__global__ __launch_bounds__(256) void qkv_kernel(
    const float* __restrict__ x,
    const float* __restrict__ w1, const float* __restrict__ w2,
    const float* __restrict__ w3,
    const float* __restrict__ bn1s, const float* __restrict__ bn1b,
    const float* __restrict__ bn1m, const float* __restrict__ bn1v,
    const float* __restrict__ bn2s, const float* __restrict__ bn2b,
    const float* __restrict__ bn2m, const float* __restrict__ bn2v,
    const float* __restrict__ bn3s, const float* __restrict__ bn3b,
    const float* __restrict__ bn3m, const float* __restrict__ bn3v)
{
    __shared__ float Xs[32][64];
    __shared__ float Ws[32][97];
    __shared__ float stage[96][65];
    __shared__ float sSc[96], sBi[96];

    const int tid = threadIdx.x;
    const int b = blockIdx.y;
    const int n0 = blockIdx.x * 64;

    if (tid < 96) {
        int grp = tid >> 5, o = tid & 31;
        const float *s_, *b_, *m_, *v_;
        if (grp == 0)      { s_ = bn1s; b_ = bn1b; m_ = bn1m; v_ = bn1v; }
        else if (grp == 1) { s_ = bn2s; b_ = bn2b; m_ = bn2m; v_ = bn2v; }
        else               { s_ = bn3s; b_ = bn3b; m_ = bn3m; v_ = bn3v; }
        float inv = s_[o] * rsqrtf(v_[o] + 1e-5f);
        sSc[tid] = inv;
        sBi[tid] = b_[o] - m_[o] * inv;
    }

    const int ty = tid >> 4;   // 0..15 : output group (6 outputs)
    const int tx = tid & 15;   // 0..15 : n group (4 positions)

    float acc[6][4];
#pragma unroll
    for (int i = 0; i < 6; i++)
#pragma unroll
        for (int j = 0; j < 4; j++) acc[i][j] = 0.f;

    for (int c0 = 0; c0 < CC; c0 += 32) {
        __syncthreads();
        // load X tile [32 c][64 n]  (512 float4 / 256 threads)
#pragma unroll
        for (int r = 0; r < 2; r++) {
            int idx = tid + r * 256;
            int cc = idx >> 4, j4 = idx & 15;
            *reinterpret_cast<float4*>(&Xs[cc][j4 * 4]) =
                *reinterpret_cast<const float4*>(
                    &x[(size_t)(b * CC + c0 + cc) * NN + n0 + j4 * 4]);
        }
        // load W tile [32 c][96 o]  (coalesced over c)
#pragma unroll
        for (int r = 0; r < 12; r++) {
            int idx = tid + r * 256;
            int cc = idx & 31, o = idx >> 5;
            const float* w = (o < 32) ? w1 : (o < 64) ? w2 : w3;
            int oo = o & 31;
            Ws[cc][o] = w[oo * CC + c0 + cc];
        }
        __syncthreads();
#pragma unroll
        for (int cc = 0; cc < 32; cc++) {
            float4 xv = *reinterpret_cast<const float4*>(&Xs[cc][tx * 4]);
#pragma unroll
            for (int i = 0; i < 6; i++) {
                float wv = Ws[cc][ty * 6 + i];
                acc[i][0] += wv * xv.x;
                acc[i][1] += wv * xv.y;
                acc[i][2] += wv * xv.z;
                acc[i][3] += wv * xv.w;
            }
        }
    }

    __syncthreads();
    // BN + ReLU into stage[o][n]
#pragma unroll
    for (int i = 0; i < 6; i++) {
        int o = ty * 6 + i;
        float sc = sSc[o], bi = sBi[o];
#pragma unroll
        for (int j = 0; j < 4; j++)
            stage[o][tx * 4 + j] = fmaxf(acc[i][j] * sc + bi, 0.f);
    }
    __syncthreads();

    // Q, K : [b][n][32], o-fast coalesced writes, tf32-rounded
#pragma unroll
    for (int r = 0; r < 16; r++) {
        int idx = tid + r * 256;
        int o = idx & 63, nl = idx >> 6;
        float v = tf32r(stage[o][nl]);
        size_t dst = ((size_t)(b * NN) + n0 + nl) * CLAT + (o & 31);
        if (o < 32) g_Q[dst] = v; else g_K[dst] = v;
    }
    // V transposed: [b][c][n] bf16, n-fast coalesced
#pragma unroll
    for (int r = 0; r < 8; r++) {
        int idx = tid + r * 256;
        int c = idx >> 6, nl = idx & 63;
        g_Vt[((size_t)(b * CLAT) + c) * NN + n0 + nl] =
            __float2bfloat16(stage[64 + c][nl]);
    }
}

// ============================================================================
// Kernel 2: flash attention.  64 query rows / CTA (4 warps x 16 rows),
// key tiles of 64, double-buffered cp.async, tf32 QK^T + bf16 PV.
// ============================================================================
__global__ __launch_bounds__(128) void attn_kernel()
{
    __shared__ float Qs[64][36];
    __shared__ float Ks[2][64][36];
    __shared__ __nv_bfloat16 Vts[2][32][72];

    const int tid = threadIdx.x;
    const int w = tid >> 5, lane = tid & 31;
    const int g = lane >> 2, t = lane & 3;
    const int b = blockIdx.y;
    const int m0 = blockIdx.x * 64;
    const float LOG2E = 1.4426950408889634f;

    // Q tile (group 0)
    const float* Qg = g_Q + ((size_t)b * NN + m0) * CLAT;
#pragma unroll
    for (int r = 0; r < 4; r++) {
        int idx = tid + r * 128;
        int row = idx >> 3, ch = idx & 7;
        cp16(sa(&Qs[row][ch * 4]), Qg + row * CLAT + ch * 4);
    }
    cpc();
    // prefetch key tile 0 (group 1)
    {
        const float* Kg = g_K + (size_t)b * NN * CLAT;
#pragma unroll
        for (int r = 0; r < 4; r++) {
            int idx = tid + r * 128;
            int row = idx >> 3, ch = idx & 7;
            cp16(sa(&Ks[0][row][ch * 4]), Kg + row * CLAT + ch * 4);
        }
        const __nv_bfloat16* Vg = g_Vt + (size_t)b * CLAT * NN;
#pragma unroll
        for (int r = 0; r < 2; r++) {
            int idx = tid + r * 128;
            int c = idx >> 3, ch = idx & 7;
            cp16(sa(&Vts[0][c][ch * 8]), Vg + (size_t)c * NN + ch * 8);
        }
    }
    cpc();
    cpw<1>();       // Q tile done
    __syncthreads();

    // Q fragments (m16n8k8 tf32 A): 4 k-steps
    uint32_t qa[4][4];
    const int r0 = w * 16 + g;
#pragma unroll
    for (int s = 0; s < 4; s++) {
        qa[s][0] = __float_as_uint(Qs[r0][8 * s + t]);
        qa[s][1] = __float_as_uint(Qs[r0 + 8][8 * s + t]);
        qa[s][2] = __float_as_uint(Qs[r0][8 * s + t + 4]);
        qa[s][3] = __float_as_uint(Qs[r0 + 8][8 * s + t + 4]);
    }

    float O[4][4];
#pragma unroll
    for (int o = 0; o < 4; o++)
#pragma unroll
        for (int j = 0; j < 4; j++) O[o][j] = 0.f;
    float mr0 = -1e30f, mr1 = -1e30f, lr0 = 0.f, lr1 = 0.f;

    const int NT = NN / 64;
    for (int kt = 0; kt < NT; kt++) {
        const int buf = kt & 1;
        __syncthreads();   // everyone done with buffer we are about to refill
        if (kt + 1 < NT) {
            const int k0 = (kt + 1) * 64;
            const int nb = (kt + 1) & 1;
            const float* Kg = g_K + ((size_t)b * NN + k0) * CLAT;
#pragma unroll
            for (int r = 0; r < 4; r++) {
                int idx = tid + r * 128;
                int row = idx >> 3, ch = idx & 7;
                cp16(sa(&Ks[nb][row][ch * 4]), Kg + row * CLAT + ch * 4);
            }
            const __nv_bfloat16* Vg = g_Vt + (size_t)b * CLAT * NN + k0;
#pragma unroll
            for (int r = 0; r < 2; r++) {
                int idx = tid + r * 128;
                int c = idx >> 3, ch = idx & 7;
                cp16(sa(&Vts[nb][c][ch * 8]), Vg + (size_t)c * NN + ch * 8);
            }
            cpc();
            cpw<1>();     // current tile (kt) landed
        } else {
            cpw<0>();
        }
        __syncthreads();

        // S = Q K^T  (8 n-tiles of 8 keys, 4 tf32 k-steps)
        float S[8][4];
#pragma unroll
        for (int j = 0; j < 8; j++)
#pragma unroll
            for (int q = 0; q < 4; q++) S[j][q] = 0.f;
#pragma unroll
        for (int s = 0; s < 4; s++) {
#pragma unroll
            for (int j = 0; j < 8; j++) {
                uint32_t b0 = __float_as_uint(Ks[buf][8 * j + g][8 * s + t]);
                uint32_t b1 = __float_as_uint(Ks[buf][8 * j + g][8 * s + t + 4]);
                mma_tf32(S[j], qa[s], b0, b1);
            }
        }

        // online softmax (rows g and g+8)
        float mt0 = -1e30f, mt1 = -1e30f;
#pragma unroll
        for (int j = 0; j < 8; j++) {
            mt0 = fmaxf(mt0, fmaxf(S[j][0], S[j][1]));
            mt1 = fmaxf(mt1, fmaxf(S[j][2], S[j][3]));
        }
        mt0 = fmaxf(mt0, __shfl_xor_sync(0xffffffffu, mt0, 1));
        mt0 = fmaxf(mt0, __shfl_xor_sync(0xffffffffu, mt0, 2));
        mt1 = fmaxf(mt1, __shfl_xor_sync(0xffffffffu, mt1, 1));
        mt1 = fmaxf(mt1, __shfl_xor_sync(0xffffffffu, mt1, 2));
        float mn0 = fmaxf(mr0, mt0), mn1 = fmaxf(mr1, mt1);
        float sc0 = ex2f((mr0 - mn0) * LOG2E);
        float sc1 = ex2f((mr1 - mn1) * LOG2E);
        mr0 = mn0; mr1 = mn1;
        lr0 *= sc0; lr1 *= sc1;
#pragma unroll
        for (int o = 0; o < 4; o++) {
            O[o][0] *= sc0; O[o][1] *= sc0;
            O[o][2] *= sc1; O[o][3] *= sc1;
        }
        float ps0 = 0.f, ps1 = 0.f;
#pragma unroll
        for (int j = 0; j < 8; j++) {
            S[j][0] = ex2f((S[j][0] - mn0) * LOG2E);
            S[j][1] = ex2f((S[j][1] - mn0) * LOG2E);
            S[j][2] = ex2f((S[j][2] - mn1) * LOG2E);
            S[j][3] = ex2f((S[j][3] - mn1) * LOG2E);
            ps0 += S[j][0] + S[j][1];
            ps1 += S[j][2] + S[j][3];
        }
        ps0 += __shfl_xor_sync(0xffffffffu, ps0, 1);
        ps0 += __shfl_xor_sync(0xffffffffu, ps0, 2);
        ps1 += __shfl_xor_sync(0xffffffffu, ps1, 1);
        ps1 += __shfl_xor_sync(0xffffffffu, ps1, 2);
        lr0 += ps0; lr1 += ps1;

        // O += P V  (bf16 m16n8k16; P converted in-register)
#pragma unroll
        for (int kk = 0; kk < 4; kk++) {
            uint32_t pa[4];
            pa[0] = pbf2(S[2 * kk][0], S[2 * kk][1]);
            pa[1] = pbf2(S[2 * kk][2], S[2 * kk][3]);
            pa[2] = pbf2(S[2 * kk + 1][0], S[2 * kk + 1][1]);
            pa[3] = pbf2(S[2 * kk + 1][2], S[2 * kk + 1][3]);
#pragma unroll
            for (int o = 0; o < 4; o++) {
                uint32_t b0 = *reinterpret_cast<const uint32_t*>(
                    &Vts[buf][8 * o + g][16 * kk + 2 * t]);
                uint32_t b1 = *reinterpret_cast<const uint32_t*>(
                    &Vts[buf][8 * o + g][16 * kk + 2 * t + 8]);
                mma_bf16(O[o], pa, b0, b1);
            }
        }
    }

    // epilogue: normalize + store agg [b][n][32]
    float i0 = 1.f / lr0, i1 = 1.f / lr1;
    const int gr0 = m0 + w * 16 + g;
    float* A0 = g_agg + ((size_t)b * NN + gr0) * CLAT;
    float* A1 = A0 + 8 * CLAT;
#pragma unroll
    for (int o = 0; o < 4; o++) {
        int c = 8 * o + 2 * t;
        *reinterpret_cast<float2*>(&A0[c]) = make_float2(O[o][0] * i0, O[o][1] * i0);
        *reinterpret_cast<float2*>(&A1[c]) = make_float2(O[o][2] * i1, O[o][3] * i1);
    }
}

// ============================================================================
// Kernel 3: out = gamma * ReLU(bn4(w_out @ agg)) + x
// Block: 128 n positions, 256 threads (2 halves x 128 output channels)
// agg row loaded per-thread from gmem (L2-resident; no smem staging tile).
// ============================================================================
__global__ __launch_bounds__(256) void proj_kernel(
    const float* __restrict__ x, const float* __restrict__ w_out,
    const float* __restrict__ bn4s, const float* __restrict__ bn4b,
    const float* __restrict__ bn4m, const float* __restrict__ bn4v,
    const float* __restrict__ gamma_p, float* __restrict__ out)
{
    __shared__ __align__(16) float Wo[CC * CLAT];
    __shared__ float sS[CC], sB[CC];

    const int tid = threadIdx.x;
    const int b = blockIdx.y;
    const int n0 = blockIdx.x * 128;

    {
        float inv = bn4s[tid] * rsqrtf(bn4v[tid] + 1e-5f);
        sS[tid] = inv;
        sB[tid] = bn4b[tid] - bn4m[tid] * inv;
    }
#pragma unroll
    for (int r = 0; r < 32; r++) Wo[tid + r * 256] = w_out[tid + r * 256];

    const int half = tid >> 7, nl = tid & 127;
    const int n = n0 + nl;

    // per-thread agg row [32 floats] straight from gmem (float4 x 8)
    float a[32];
    {
        const float4* Ag = reinterpret_cast<const float4*>(
            g_agg + ((size_t)b * NN + n) * CLAT);
#pragma unroll
        for (int c4 = 0; c4 < 8; c4++) {
            float4 v = Ag[c4];
            a[c4 * 4] = v.x; a[c4 * 4 + 1] = v.y;
            a[c4 * 4 + 2] = v.z; a[c4 * 4 + 3] = v.w;
        }
    }
    __syncthreads();

    const float gamma = *gamma_p;
    const float4* Wo4 = reinterpret_cast<const float4*>(Wo);
#pragma unroll 4
    for (int oo = 0; oo < 128; oo++) {
        int o = half * 128 + oo;
        float d = 0.f;
#pragma unroll
        for (int c4 = 0; c4 < 8; c4++) {
            float4 wv = Wo4[o * 8 + c4];
            d += wv.x * a[c4 * 4] + wv.y * a[c4 * 4 + 1] +
                 wv.z * a[c4 * 4 + 2] + wv.w * a[c4 * 4 + 3];
        }
        float r = fmaxf(d * sS[o] + sB[o], 0.f);
        size_t gi = ((size_t)(b * CC + o)) * NN + n;
        out[gi] = gamma * r + x[gi];
    }
}

// ============================================================================
extern "C" void kernel_launch(void* const* d_in, const int* in_sizes, int n_in,
                              void* d_out, int out_size)
{
    const float* x    = (const float*)d_in[0];
    const float* w1   = (const float*)d_in[1];
    const float* w2   = (const float*)d_in[2];
    const float* w3   = (const float*)d_in[3];
    const float* wout = (const float*)d_in[4];
    const float* bn1s = (const float*)d_in[5];
    const float* bn1b = (const float*)d_in[6];
    const float* bn1m = (const float*)d_in[7];
    const float* bn1v = (const float*)d_in[8];
    const float* bn2s = (const float*)d_in[9];
    const float* bn2b = (const float*)d_in[10];
    const float* bn2m = (const float*)d_in[11];
    const float* bn2v = (const float*)d_in[12];
    const float* bn3s = (const float*)d_in[13];
    const float* bn3b = (const float*)d_in[14];
    const float* bn3m = (const float*)d_in[15];
    const float* bn3v = (const float*)d_in[16];
    const float* bn4s = (const float*)d_in[17];
    const float* bn4b = (const float*)d_in[18];
    const float* bn4m = (const float*)d_in[19];
    const float* bn4v = (const float*)d_in[20];
    const float* gam  = (const float*)d_in[21];
    float* out = (float*)d_out;

    qkv_kernel<<<dim3(NN / 64, BB), 256>>>(x, w1, w2, w3,
                                           bn1s, bn1b, bn1m, bn1v,
                                           bn2s, bn2b, bn2m, bn2v,
                                           bn3s, bn3b, bn3m, bn3v);
    attn_kernel<<<dim3(NN / 64, BB), 128>>>();
    proj_kernel<<<dim3(NN / 128, BB), 256>>>(x, wout, bn4s, bn4b, bn4m, bn4v,
                                             gam, out);
}

// round 3
// speedup vs baseline: 1.2827x; 1.2827x over previous
#include <cuda_runtime.h>
#include <cuda_bf16.h>
#include <cstdint>

// Problem constants
#define BB 4
#define CC 256
#define CLAT 32
#define NN 4096

// Scratch (device globals -- no allocation allowed)
__device__ float g_Q[BB * NN * CLAT];              // [b][n][32] tf32-rounded
__device__ float g_K[BB * NN * CLAT];              // [b][n][32] tf32-rounded
__device__ __nv_bfloat16 g_Vt[BB * CLAT * NN];     // [b][c][n] bf16
__device__ float g_agg[BB * NN * CLAT];            // [b][n][32] fp32
// split-K attention partials
__device__ float g_pO[2][BB * NN * CLAT];          // unnormalized O
__device__ float g_pm[2][BB * NN];
__device__ float g_pl[2][BB * NN];

// ---------------- helpers ----------------
__device__ __forceinline__ uint32_t sa(const void* p) {
    return (uint32_t)__cvta_generic_to_shared(p);
}
__device__ __forceinline__ void cp16(uint32_t s, const void* g) {
    asm volatile("cp.async.cg.shared.global [%0],[%1],16;\n" :: "r"(s), "l"(g));
}
__device__ __forceinline__ void cpc() { asm volatile("cp.async.commit_group;\n"); }
template <int W> __device__ __forceinline__ void cpw() {
    asm volatile("cp.async.wait_group %0;\n" :: "n"(W));
}
__device__ __forceinline__ float ex2f(float x) {
    float y; asm("ex2.approx.f32 %0,%1;" : "=f"(y) : "f"(x)); return y;
}
__device__ __forceinline__ float tf32r(float x) {
    uint32_t u; asm("cvt.rna.tf32.f32 %0,%1;" : "=r"(u) : "f"(x));
    return __uint_as_float(u);
}
__device__ __forceinline__ uint32_t pbf2(float lo, float hi) {
    uint32_t r; asm("cvt.rn.bf16x2.f32 %0,%1,%2;" : "=r"(r) : "f"(hi), "f"(lo));
    return r;
}
__device__ __forceinline__ void mma_tf32(float d[4], const uint32_t a[4],
                                         uint32_t b0, uint32_t b1) {
    asm volatile(
        "mma.sync.aligned.m16n8k8.row.col.f32.tf32.tf32.f32 "
        "{%0,%1,%2,%3},{%4,%5,%6,%7},{%8,%9},{%0,%1,%2,%3};\n"
        : "+f"(d[0]), "+f"(d[1]), "+f"(d[2]), "+f"(d[3])
        : "r"(a[0]), "r"(a[1]), "r"(a[2]), "r"(a[3]), "r"(b0), "r"(b1));
}
__device__ __forceinline__ void mma_bf16(float d[4], const uint32_t a[4],
                                         uint32_t b0, uint32_t b1) {
    asm volatile(
        "mma.sync.aligned.m16n8k16.row.col.f32.bf16.bf16.f32 "
        "{%0,%1,%2,%3},{%4,%5,%6,%7},{%8,%9},{%0,%1,%2,%3};\n"
        : "+f"(d[0]), "+f"(d[1]), "+f"(d[2]), "+f"(d[3])
        : "r"(a[0]), "r"(a[1]), "r"(a[2]), "r"(a[3]), "r"(b0), "r"(b1));
}

// ============================================================================
// Kernel 1: QKV projection via tf32 mma.sync.
// CTA: 64 n x 96 outputs, K=256. 256 threads (8 warps):
//   warp w -> rows16 = (w&3)*16, output half jbase = (w>>2)*6 (6 j-tiles of 8).
// W staged fully in smem (tf32-rounded), X prefetched 4 chunks deep (cp.async).
// Dynamic smem: Ws[96][260] + Xs[4][64][72] + bn params = 174336 B.
// ============================================================================
__global__ __launch_bounds__(256, 1) void qkv_mma(
    const float* __restrict__ x,
    const float* __restrict__ w1, const float* __restrict__ w2,
    const float* __restrict__ w3,
    const float* __restrict__ bn1s, const float* __restrict__ bn1b,
    const float* __restrict__ bn1m, const float* __restrict__ bn1v,
    const float* __restrict__ bn2s, const float* __restrict__ bn2b,
    const float* __restrict__ bn2m, const float* __restrict__ bn2v,
    const float* __restrict__ bn3s, const float* __restrict__ bn3b,
    const float* __restrict__ bn3m, const float* __restrict__ bn3v)
{
    extern __shared__ char sm[];
    float* Ws  = (float*)sm;                         // [96][260]
    float* Xs  = (float*)(sm + 99840);               // [4][64][72]
    float* sSc = (float*)(sm + 173568);              // [96]
    float* sBi = (float*)(sm + 173952);              // [96]
    __nv_bfloat16* Vst = (__nv_bfloat16*)(sm + 99840); // reuse Xs: [32][72]

    const int tid = threadIdx.x;
    const int b = blockIdx.y;
    const int n0 = blockIdx.x * 64;

    if (tid < 96) {
        int grp = tid >> 5, o = tid & 31;
        const float *s_, *b_, *m_, *v_;
        if (grp == 0)      { s_ = bn1s; b_ = bn1b; m_ = bn1m; v_ = bn1v; }
        else if (grp == 1) { s_ = bn2s; b_ = bn2b; m_ = bn2m; v_ = bn2v; }
        else               { s_ = bn3s; b_ = bn3b; m_ = bn3m; v_ = bn3v; }
        float inv = s_[o] * rsqrtf(v_[o] + 1e-5f);
        sSc[tid] = inv;
        sBi[tid] = b_[o] - m_[o] * inv;
    }

    // Stage W (96x256) -> Ws[o][260], tf32-rounded. 6144 float4 / 256 thr = 24.
#pragma unroll
    for (int r = 0; r < 24; r++) {
        int idx = tid + r * 256;
        int o = idx >> 6, c4 = idx & 63;
        const float* w = (o < 32) ? w1 : (o < 64) ? w2 : w3;
        float4 v = *reinterpret_cast<const float4*>(&w[(o & 31) * CC + c4 * 4]);
        float4 t;
        t.x = tf32r(v.x); t.y = tf32r(v.y); t.z = tf32r(v.z); t.w = tf32r(v.w);
        *reinterpret_cast<float4*>(&Ws[o * 260 + c4 * 4]) = t;
    }

    // Prefetch all 4 X chunks: chunk ch = c rows [64ch, 64ch+64), 64 n each.
#pragma unroll
    for (int ch = 0; ch < 4; ch++) {
#pragma unroll
        for (int r = 0; r < 4; r++) {
            int idx = tid + r * 256;
            int cc = idx >> 4, c4 = idx & 15;
            cp16(sa(&Xs[ch * 4608 + cc * 72 + c4 * 4]),
                 &x[(size_t)(b * CC + ch * 64 + cc) * NN + n0 + c4 * 4]);
        }
        cpc();
    }

    const int w = tid >> 5, lane = tid & 31;
    const int g = lane >> 2, t = lane & 3;
    const int rows16 = (w & 3) * 16;
    const int jbase = (w >> 2) * 6;

    float C[6][4];
#pragma unroll
    for (int j = 0; j < 6; j++)
#pragma unroll
        for (int q = 0; q < 4; q++) C[j][q] = 0.f;

#pragma unroll
    for (int ch = 0; ch < 4; ch++) {
        if (ch == 0) cpw<3>();
        else if (ch == 1) cpw<2>();
        else if (ch == 2) cpw<1>();
        else cpw<0>();
        __syncthreads();
        const float* Xc = &Xs[ch * 4608];
#pragma unroll
        for (int s = 0; s < 8; s++) {
            uint32_t a[4];
            int cl = s * 8 + t;
            a[0] = __float_as_uint(tf32r(Xc[cl * 72 + rows16 + g]));
            a[1] = __float_as_uint(tf32r(Xc[cl * 72 + rows16 + g + 8]));
            a[2] = __float_as_uint(tf32r(Xc[(cl + 4) * 72 + rows16 + g]));
            a[3] = __float_as_uint(tf32r(Xc[(cl + 4) * 72 + rows16 + g + 8]));
            int cg = ch * 64 + s * 8;
#pragma unroll
            for (int jj = 0; jj < 6; jj++) {
                int o = (jbase + jj) * 8 + g;
                uint32_t b0 = __float_as_uint(Ws[o * 260 + cg + t]);
                uint32_t b1 = __float_as_uint(Ws[o * 260 + cg + t + 4]);
                mma_tf32(C[jj], a, b0, b1);
            }
        }
    }
    __syncthreads();   // done reading Xs; Vst may reuse it

    // Epilogue: BN + ReLU, route to Q / K / Vst
    const int n_a = n0 + rows16 + g;
    const int n_b = n_a + 8;
#pragma unroll
    for (int jj = 0; jj < 6; jj++) {
        int ob = (jbase + jj) * 8 + 2 * t;
        float sc0 = sSc[ob], bi0 = sBi[ob];
        float sc1 = sSc[ob + 1], bi1 = sBi[ob + 1];
        float v00 = fmaxf(C[jj][0] * sc0 + bi0, 0.f);
        float v01 = fmaxf(C[jj][1] * sc1 + bi1, 0.f);
        float v10 = fmaxf(C[jj][2] * sc0 + bi0, 0.f);
        float v11 = fmaxf(C[jj][3] * sc1 + bi1, 0.f);
        if (ob < 64) {
            float* dst = (ob < 32) ? g_Q : g_K;
            int oc = ob & 31;
            *reinterpret_cast<float2*>(&dst[((size_t)(b * NN) + n_a) * CLAT + oc]) =
                make_float2(tf32r(v00), tf32r(v01));
            *reinterpret_cast<float2*>(&dst[((size_t)(b * NN) + n_b) * CLAT + oc]) =
                make_float2(tf32r(v10), tf32r(v11));
        } else {
            int c = ob - 64;
            int nl = rows16 + g;
            Vst[c * 72 + nl]           = __float2bfloat16(v00);
            Vst[(c + 1) * 72 + nl]     = __float2bfloat16(v01);
            Vst[c * 72 + nl + 8]       = __float2bfloat16(v10);
            Vst[(c + 1) * 72 + nl + 8] = __float2bfloat16(v11);
        }
    }
    __syncthreads();
    // coalesced V flush: 32 c x 32 bf16x2
#pragma unroll
    for (int r = 0; r < 4; r++) {
        int idx = tid + r * 256;
        int c = idx >> 5, n2 = idx & 31;
        __nv_bfloat162 p;
        p.x = Vst[c * 72 + 2 * n2];
        p.y = Vst[c * 72 + 2 * n2 + 1];
        *reinterpret_cast<__nv_bfloat162*>(
            &g_Vt[((size_t)(b * CLAT) + c) * NN + n0 + 2 * n2]) = p;
    }
}

// ============================================================================
// Kernel 2: flash attention, split-K = 2.
// CTA: 64 queries (4 warps x 16 rows) x 2048 keys (16 tiles of 128).
// Writes unnormalized O + (m,l) partials.  Dynamic smem 63488 B.
// ============================================================================
__global__ __launch_bounds__(128) void attn_kernel()
{
    extern __shared__ char sm[];
    float (*Qs)[36]        = (float(*)[36])sm;                      // [64][36]
    float (*Ks)[128][36]   = (float(*)[128][36])(sm + 9216);        // [2][128][36]
    __nv_bfloat16 (*Vts)[32][136] =
        (__nv_bfloat16(*)[32][136])(sm + 46080);                    // [2][32][136]

    const int tid = threadIdx.x;
    const int w = tid >> 5, lane = tid & 31;
    const int g = lane >> 2, t = lane & 3;
    const int b = blockIdx.y;
    const int m0 = blockIdx.x * 64;
    const int kz = blockIdx.z;
    const int kbase = kz * 2048;
    const float LOG2E = 1.4426950408889634f;

    // Q tile (group 0)
    const float* Qg = g_Q + ((size_t)b * NN + m0) * CLAT;
#pragma unroll
    for (int r = 0; r < 4; r++) {
        int idx = tid + r * 128;
        int row = idx >> 3, ch = idx & 7;
        cp16(sa(&Qs[row][ch * 4]), Qg + row * CLAT + ch * 4);
    }
    cpc();
    // prefetch K/V tile 0 (group 1)
    {
        const float* Kg = g_K + ((size_t)b * NN + kbase) * CLAT;
#pragma unroll
        for (int r = 0; r < 8; r++) {
            int idx = tid + r * 128;
            int row = idx >> 3, ch = idx & 7;
            cp16(sa(&Ks[0][row][ch * 4]), Kg + row * CLAT + ch * 4);
        }
        const __nv_bfloat16* Vg = g_Vt + (size_t)b * CLAT * NN + kbase;
#pragma unroll
        for (int r = 0; r < 4; r++) {
            int idx = tid + r * 128;
            int c = idx >> 4, ch = idx & 15;
            cp16(sa(&Vts[0][c][ch * 8]), Vg + (size_t)c * NN + ch * 8);
        }
    }
    cpc();
    cpw<1>();
    __syncthreads();

    uint32_t qa[4][4];
    const int r0 = w * 16 + g;
#pragma unroll
    for (int s = 0; s < 4; s++) {
        qa[s][0] = __float_as_uint(Qs[r0][8 * s + t]);
        qa[s][1] = __float_as_uint(Qs[r0 + 8][8 * s + t]);
        qa[s][2] = __float_as_uint(Qs[r0][8 * s + t + 4]);
        qa[s][3] = __float_as_uint(Qs[r0 + 8][8 * s + t + 4]);
    }

    float O[4][4];
#pragma unroll
    for (int o = 0; o < 4; o++)
#pragma unroll
        for (int j = 0; j < 4; j++) O[o][j] = 0.f;
    float mr0 = -1e30f, mr1 = -1e30f, lr0 = 0.f, lr1 = 0.f;

    const int NT = 2048 / 128;   // 16 tiles
    for (int kt = 0; kt < NT; kt++) {
        const int buf = kt & 1;
        __syncthreads();
        if (kt + 1 < NT) {
            const int k0 = kbase + (kt + 1) * 128;
            const int nb = (kt + 1) & 1;
            const float* Kg = g_K + ((size_t)b * NN + k0) * CLAT;
#pragma unroll
            for (int r = 0; r < 8; r++) {
                int idx = tid + r * 128;
                int row = idx >> 3, ch = idx & 7;
                cp16(sa(&Ks[nb][row][ch * 4]), Kg + row * CLAT + ch * 4);
            }
            const __nv_bfloat16* Vg = g_Vt + (size_t)b * CLAT * NN + k0;
#pragma unroll
            for (int r = 0; r < 4; r++) {
                int idx = tid + r * 128;
                int c = idx >> 4, ch = idx & 15;
                cp16(sa(&Vts[nb][c][ch * 8]), Vg + (size_t)c * NN + ch * 8);
            }
            cpc();
            cpw<1>();
        } else {
            cpw<0>();
        }
        __syncthreads();

        // S = Q K^T  (16 j-tiles of 8 keys)
        float S[16][4];
#pragma unroll
        for (int j = 0; j < 16; j++)
#pragma unroll
            for (int q = 0; q < 4; q++) S[j][q] = 0.f;
#pragma unroll
        for (int s = 0; s < 4; s++) {
#pragma unroll
            for (int j = 0; j < 16; j++) {
                uint32_t b0 = __float_as_uint(Ks[buf][8 * j + g][8 * s + t]);
                uint32_t b1 = __float_as_uint(Ks[buf][8 * j + g][8 * s + t + 4]);
                mma_tf32(S[j], qa[s], b0, b1);
            }
        }

        // online softmax
        float mt0 = -1e30f, mt1 = -1e30f;
#pragma unroll
        for (int j = 0; j < 16; j++) {
            mt0 = fmaxf(mt0, fmaxf(S[j][0], S[j][1]));
            mt1 = fmaxf(mt1, fmaxf(S[j][2], S[j][3]));
        }
        mt0 = fmaxf(mt0, __shfl_xor_sync(0xffffffffu, mt0, 1));
        mt0 = fmaxf(mt0, __shfl_xor_sync(0xffffffffu, mt0, 2));
        mt1 = fmaxf(mt1, __shfl_xor_sync(0xffffffffu, mt1, 1));
        mt1 = fmaxf(mt1, __shfl_xor_sync(0xffffffffu, mt1, 2));
        float mn0 = fmaxf(mr0, mt0), mn1 = fmaxf(mr1, mt1);
        float sc0 = ex2f((mr0 - mn0) * LOG2E);
        float sc1 = ex2f((mr1 - mn1) * LOG2E);
        mr0 = mn0; mr1 = mn1;
        lr0 *= sc0; lr1 *= sc1;
#pragma unroll
        for (int o = 0; o < 4; o++) {
            O[o][0] *= sc0; O[o][1] *= sc0;
            O[o][2] *= sc1; O[o][3] *= sc1;
        }
        float ps0 = 0.f, ps1 = 0.f;
#pragma unroll
        for (int j = 0; j < 16; j++) {
            S[j][0] = ex2f((S[j][0] - mn0) * LOG2E);
            S[j][1] = ex2f((S[j][1] - mn0) * LOG2E);
            S[j][2] = ex2f((S[j][2] - mn1) * LOG2E);
            S[j][3] = ex2f((S[j][3] - mn1) * LOG2E);
            ps0 += S[j][0] + S[j][1];
            ps1 += S[j][2] + S[j][3];
        }
        ps0 += __shfl_xor_sync(0xffffffffu, ps0, 1);
        ps0 += __shfl_xor_sync(0xffffffffu, ps0, 2);
        ps1 += __shfl_xor_sync(0xffffffffu, ps1, 1);
        ps1 += __shfl_xor_sync(0xffffffffu, ps1, 2);
        lr0 += ps0; lr1 += ps1;

        // O += P V
#pragma unroll
        for (int kk = 0; kk < 8; kk++) {
            uint32_t pa[4];
            pa[0] = pbf2(S[2 * kk][0], S[2 * kk][1]);
            pa[1] = pbf2(S[2 * kk][2], S[2 * kk][3]);
            pa[2] = pbf2(S[2 * kk + 1][0], S[2 * kk + 1][1]);
            pa[3] = pbf2(S[2 * kk + 1][2], S[2 * kk + 1][3]);
#pragma unroll
            for (int o = 0; o < 4; o++) {
                uint32_t b0 = *reinterpret_cast<const uint32_t*>(
                    &Vts[buf][8 * o + g][16 * kk + 2 * t]);
                uint32_t b1 = *reinterpret_cast<const uint32_t*>(
                    &Vts[buf][8 * o + g][16 * kk + 2 * t + 8]);
                mma_bf16(O[o], pa, b0, b1);
            }
        }
    }

    // epilogue: store UNNORMALIZED partials + (m, l)
    const int n_a = m0 + w * 16 + g;
    const int n_b = n_a + 8;
    float* P = g_pO[kz] + ((size_t)b * NN + n_a) * CLAT;
    float* Pb = g_pO[kz] + ((size_t)b * NN + n_b) * CLAT;
#pragma unroll
    for (int o = 0; o < 4; o++) {
        int c = 8 * o + 2 * t;
        *reinterpret_cast<float2*>(&P[c])  = make_float2(O[o][0], O[o][1]);
        *reinterpret_cast<float2*>(&Pb[c]) = make_float2(O[o][2], O[o][3]);
    }
    if (t == 0) {
        g_pm[kz][b * NN + n_a] = mr0;
        g_pl[kz][b * NN + n_a] = lr0;
        g_pm[kz][b * NN + n_b] = mr1;
        g_pl[kz][b * NN + n_b] = lr1;
    }
}

// ============================================================================
// Kernel 2b: combine split-K partials -> g_agg
// ============================================================================
__global__ __launch_bounds__(256) void combine_kernel()
{
    const int wid = threadIdx.x >> 5, lane = threadIdx.x & 31;
    const int row = blockIdx.x * 8 + wid;   // 0..16383  (b*NN + n)
    const float LOG2E = 1.4426950408889634f;
    float m0 = g_pm[0][row], m1 = g_pm[1][row];
    float l0 = g_pl[0][row], l1 = g_pl[1][row];
    float m = fmaxf(m0, m1);
    float e0 = ex2f((m0 - m) * LOG2E);
    float e1 = ex2f((m1 - m) * LOG2E);
    float inv = 1.f / (l0 * e0 + l1 * e1);
    size_t base = (size_t)row * CLAT + lane;
    g_agg[base] = (g_pO[0][base] * e0 + g_pO[1][base] * e1) * inv;
}

// ============================================================================
// Kernel 3: out = gamma * ReLU(bn4(w_out @ agg)) + x
// ============================================================================
__global__ __launch_bounds__(256) void proj_kernel(
    const float* __restrict__ x, const float* __restrict__ w_out,
    const float* __restrict__ bn4s, const float* __restrict__ bn4b,
    const float* __restrict__ bn4m, const float* __restrict__ bn4v,
    const float* __restrict__ gamma_p, float* __restrict__ out)
{
    __shared__ __align__(16) float Wo[CC * CLAT];
    __shared__ float sS[CC], sB[CC];

    const int tid = threadIdx.x;
    const int b = blockIdx.y;
    const int n0 = blockIdx.x * 128;

    {
        float inv = bn4s[tid] * rsqrtf(bn4v[tid] + 1e-5f);
        sS[tid] = inv;
        sB[tid] = bn4b[tid] - bn4m[tid] * inv;
    }
#pragma unroll
    for (int r = 0; r < 32; r++) Wo[tid + r * 256] = w_out[tid + r * 256];

    const int half = tid >> 7, nl = tid & 127;
    const int n = n0 + nl;

    float a[32];
    {
        const float4* Ag = reinterpret_cast<const float4*>(
            g_agg + ((size_t)b * NN + n) * CLAT);
#pragma unroll
        for (int c4 = 0; c4 < 8; c4++) {
            float4 v = Ag[c4];
            a[c4 * 4] = v.x; a[c4 * 4 + 1] = v.y;
            a[c4 * 4 + 2] = v.z; a[c4 * 4 + 3] = v.w;
        }
    }
    __syncthreads();

    const float gamma = *gamma_p;
    const float4* Wo4 = reinterpret_cast<const float4*>(Wo);
#pragma unroll 4
    for (int oo = 0; oo < 128; oo++) {
        int o = half * 128 + oo;
        float d = 0.f;
#pragma unroll
        for (int c4 = 0; c4 < 8; c4++) {
            float4 wv = Wo4[o * 8 + c4];
            d += wv.x * a[c4 * 4] + wv.y * a[c4 * 4 + 1] +
                 wv.z * a[c4 * 4 + 2] + wv.w * a[c4 * 4 + 3];
        }
        float r = fmaxf(d * sS[o] + sB[o], 0.f);
        size_t gi = ((size_t)(b * CC + o)) * NN + n;
        out[gi] = gamma * r + x[gi];
    }
}

// ============================================================================
extern "C" void kernel_launch(void* const* d_in, const int* in_sizes, int n_in,
                              void* d_out, int out_size)
{
    const float* x    = (const float*)d_in[0];
    const float* w1   = (const float*)d_in[1];
    const float* w2   = (const float*)d_in[2];
    const float* w3   = (const float*)d_in[3];
    const float* wout = (const float*)d_in[4];
    const float* bn1s = (const float*)d_in[5];
    const float* bn1b = (const float*)d_in[6];
    const float* bn1m = (const float*)d_in[7];
    const float* bn1v = (const float*)d_in[8];
    const float* bn2s = (const float*)d_in[9];
    const float* bn2b = (const float*)d_in[10];
    const float* bn2m = (const float*)d_in[11];
    const float* bn2v = (const float*)d_in[12];
    const float* bn3s = (const float*)d_in[13];
    const float* bn3b = (const float*)d_in[14];
    const float* bn3m = (const float*)d_in[15];
    const float* bn3v = (const float*)d_in[16];
    const float* bn4s = (const float*)d_in[17];
    const float* bn4b = (const float*)d_in[18];
    const float* bn4m = (const float*)d_in[19];
    const float* bn4v = (const float*)d_in[20];
    const float* gam  = (const float*)d_in[21];
    float* out = (float*)d_out;

    const int QKV_SMEM = 174336;
    const int ATTN_SMEM = 63488;
    cudaFuncSetAttribute(qkv_mma, cudaFuncAttributeMaxDynamicSharedMemorySize,
                         QKV_SMEM);
    cudaFuncSetAttribute(attn_kernel, cudaFuncAttributeMaxDynamicSharedMemorySize,
                         ATTN_SMEM);

    qkv_mma<<<dim3(NN / 64, BB), 256, QKV_SMEM>>>(x, w1, w2, w3,
                                                  bn1s, bn1b, bn1m, bn1v,
                                                  bn2s, bn2b, bn2m, bn2v,
                                                  bn3s, bn3b, bn3m, bn3v);
    attn_kernel<<<dim3(NN / 64, BB, 2), 128, ATTN_SMEM>>>();
    combine_kernel<<<BB * NN / 8, 256>>>();
    proj_kernel<<<dim3(NN / 128, BB), 256>>>(x, wout, bn4s, bn4b, bn4m, bn4v,
                                             gam, out);
}

// round 4
// speedup vs baseline: 1.3427x; 1.0468x over previous
#include <cuda_runtime.h>
#include <cuda_bf16.h>
#include <cstdint>

// Problem constants
#define BB 4
#define CC 256
#define CLAT 32
#define NN 4096

// Scratch (device globals -- no allocation allowed)
__device__ float g_Q[BB * NN * CLAT];              // [b][n][32] tf32-rounded
__device__ float g_K[BB * NN * CLAT];              // [b][n][32] tf32-rounded
__device__ __nv_bfloat16 g_Vt[BB * CLAT * NN];     // [b][c][n] bf16
// split-K attention partials
__device__ float g_pO[2][BB * NN * CLAT];          // unnormalized O
__device__ float g_pm[2][BB * NN];
__device__ float g_pl[2][BB * NN];

// ---------------- helpers ----------------
__device__ __forceinline__ uint32_t sa(const void* p) {
    return (uint32_t)__cvta_generic_to_shared(p);
}
__device__ __forceinline__ void cp16(uint32_t s, const void* g) {
    asm volatile("cp.async.cg.shared.global [%0],[%1],16;\n" :: "r"(s), "l"(g));
}
__device__ __forceinline__ void cpc() { asm volatile("cp.async.commit_group;\n"); }
template <int W> __device__ __forceinline__ void cpw() {
    asm volatile("cp.async.wait_group %0;\n" :: "n"(W));
}
__device__ __forceinline__ float ex2f(float x) {
    float y; asm("ex2.approx.f32 %0,%1;" : "=f"(y) : "f"(x)); return y;
}
__device__ __forceinline__ float tf32r(float x) {
    uint32_t u; asm("cvt.rna.tf32.f32 %0,%1;" : "=r"(u) : "f"(x));
    return __uint_as_float(u);
}
__device__ __forceinline__ uint32_t pbf2(float lo, float hi) {
    uint32_t r; asm("cvt.rn.bf16x2.f32 %0,%1,%2;" : "=r"(r) : "f"(hi), "f"(lo));
    return r;
}
__device__ __forceinline__ void mma_tf32(float d[4], const uint32_t a[4],
                                         uint32_t b0, uint32_t b1) {
    asm volatile(
        "mma.sync.aligned.m16n8k8.row.col.f32.tf32.tf32.f32 "
        "{%0,%1,%2,%3},{%4,%5,%6,%7},{%8,%9},{%0,%1,%2,%3};\n"
        : "+f"(d[0]), "+f"(d[1]), "+f"(d[2]), "+f"(d[3])
        : "r"(a[0]), "r"(a[1]), "r"(a[2]), "r"(a[3]), "r"(b0), "r"(b1));
}
__device__ __forceinline__ void mma_bf16(float d[4], const uint32_t a[4],
                                         uint32_t b0, uint32_t b1) {
    asm volatile(
        "mma.sync.aligned.m16n8k16.row.col.f32.bf16.bf16.f32 "
        "{%0,%1,%2,%3},{%4,%5,%6,%7},{%8,%9},{%0,%1,%2,%3};\n"
        : "+f"(d[0]), "+f"(d[1]), "+f"(d[2]), "+f"(d[3])
        : "r"(a[0]), "r"(a[1]), "r"(a[2]), "r"(a[3]), "r"(b0), "r"(b1));
}

// ============================================================================
// Kernel 1: QKV projection via tf32 mma.sync (unchanged from R3).
// ============================================================================
__global__ __launch_bounds__(256, 1) void qkv_mma(
    const float* __restrict__ x,
    const float* __restrict__ w1, const float* __restrict__ w2,
    const float* __restrict__ w3,
    const float* __restrict__ bn1s, const float* __restrict__ bn1b,
    const float* __restrict__ bn1m, const float* __restrict__ bn1v,
    const float* __restrict__ bn2s, const float* __restrict__ bn2b,
    const float* __restrict__ bn2m, const float* __restrict__ bn2v,
    const float* __restrict__ bn3s, const float* __restrict__ bn3b,
    const float* __restrict__ bn3m, const float* __restrict__ bn3v)
{
    extern __shared__ char sm[];
    float* Ws  = (float*)sm;                         // [96][260]
    float* Xs  = (float*)(sm + 99840);               // [4][64][72]
    float* sSc = (float*)(sm + 173568);              // [96]
    float* sBi = (float*)(sm + 173952);              // [96]
    __nv_bfloat16* Vst = (__nv_bfloat16*)(sm + 99840); // reuse Xs: [32][72]

    const int tid = threadIdx.x;
    const int b = blockIdx.y;
    const int n0 = blockIdx.x * 64;

    if (tid < 96) {
        int grp = tid >> 5, o = tid & 31;
        const float *s_, *b_, *m_, *v_;
        if (grp == 0)      { s_ = bn1s; b_ = bn1b; m_ = bn1m; v_ = bn1v; }
        else if (grp == 1) { s_ = bn2s; b_ = bn2b; m_ = bn2m; v_ = bn2v; }
        else               { s_ = bn3s; b_ = bn3b; m_ = bn3m; v_ = bn3v; }
        float inv = s_[o] * rsqrtf(v_[o] + 1e-5f);
        sSc[tid] = inv;
        sBi[tid] = b_[o] - m_[o] * inv;
    }

#pragma unroll
    for (int r = 0; r < 24; r++) {
        int idx = tid + r * 256;
        int o = idx >> 6, c4 = idx & 63;
        const float* w = (o < 32) ? w1 : (o < 64) ? w2 : w3;
        float4 v = *reinterpret_cast<const float4*>(&w[(o & 31) * CC + c4 * 4]);
        float4 t;
        t.x = tf32r(v.x); t.y = tf32r(v.y); t.z = tf32r(v.z); t.w = tf32r(v.w);
        *reinterpret_cast<float4*>(&Ws[o * 260 + c4 * 4]) = t;
    }

#pragma unroll
    for (int ch = 0; ch < 4; ch++) {
#pragma unroll
        for (int r = 0; r < 4; r++) {
            int idx = tid + r * 256;
            int cc = idx >> 4, c4 = idx & 15;
            cp16(sa(&Xs[ch * 4608 + cc * 72 + c4 * 4]),
                 &x[(size_t)(b * CC + ch * 64 + cc) * NN + n0 + c4 * 4]);
        }
        cpc();
    }

    const int w = tid >> 5, lane = tid & 31;
    const int g = lane >> 2, t = lane & 3;
    const int rows16 = (w & 3) * 16;
    const int jbase = (w >> 2) * 6;

    float C[6][4];
#pragma unroll
    for (int j = 0; j < 6; j++)
#pragma unroll
        for (int q = 0; q < 4; q++) C[j][q] = 0.f;

#pragma unroll
    for (int ch = 0; ch < 4; ch++) {
        if (ch == 0) cpw<3>();
        else if (ch == 1) cpw<2>();
        else if (ch == 2) cpw<1>();
        else cpw<0>();
        __syncthreads();
        const float* Xc = &Xs[ch * 4608];
#pragma unroll
        for (int s = 0; s < 8; s++) {
            uint32_t a[4];
            int cl = s * 8 + t;
            a[0] = __float_as_uint(tf32r(Xc[cl * 72 + rows16 + g]));
            a[1] = __float_as_uint(tf32r(Xc[cl * 72 + rows16 + g + 8]));
            a[2] = __float_as_uint(tf32r(Xc[(cl + 4) * 72 + rows16 + g]));
            a[3] = __float_as_uint(tf32r(Xc[(cl + 4) * 72 + rows16 + g + 8]));
            int cg = ch * 64 + s * 8;
#pragma unroll
            for (int jj = 0; jj < 6; jj++) {
                int o = (jbase + jj) * 8 + g;
                uint32_t b0 = __float_as_uint(Ws[o * 260 + cg + t]);
                uint32_t b1 = __float_as_uint(Ws[o * 260 + cg + t + 4]);
                mma_tf32(C[jj], a, b0, b1);
            }
        }
    }
    __syncthreads();

    const int n_a = n0 + rows16 + g;
    const int n_b = n_a + 8;
#pragma unroll
    for (int jj = 0; jj < 6; jj++) {
        int ob = (jbase + jj) * 8 + 2 * t;
        float sc0 = sSc[ob], bi0 = sBi[ob];
        float sc1 = sSc[ob + 1], bi1 = sBi[ob + 1];
        float v00 = fmaxf(C[jj][0] * sc0 + bi0, 0.f);
        float v01 = fmaxf(C[jj][1] * sc1 + bi1, 0.f);
        float v10 = fmaxf(C[jj][2] * sc0 + bi0, 0.f);
        float v11 = fmaxf(C[jj][3] * sc1 + bi1, 0.f);
        if (ob < 64) {
            float* dst = (ob < 32) ? g_Q : g_K;
            int oc = ob & 31;
            *reinterpret_cast<float2*>(&dst[((size_t)(b * NN) + n_a) * CLAT + oc]) =
                make_float2(tf32r(v00), tf32r(v01));
            *reinterpret_cast<float2*>(&dst[((size_t)(b * NN) + n_b) * CLAT + oc]) =
                make_float2(tf32r(v10), tf32r(v11));
        } else {
            int c = ob - 64;
            int nl = rows16 + g;
            Vst[c * 72 + nl]           = __float2bfloat16(v00);
            Vst[(c + 1) * 72 + nl]     = __float2bfloat16(v01);
            Vst[c * 72 + nl + 8]       = __float2bfloat16(v10);
            Vst[(c + 1) * 72 + nl + 8] = __float2bfloat16(v11);
        }
    }
    __syncthreads();
#pragma unroll
    for (int r = 0; r < 4; r++) {
        int idx = tid + r * 256;
        int c = idx >> 5, n2 = idx & 31;
        __nv_bfloat162 p;
        p.x = Vst[c * 72 + 2 * n2];
        p.y = Vst[c * 72 + 2 * n2 + 1];
        *reinterpret_cast<__nv_bfloat162*>(
            &g_Vt[((size_t)(b * CLAT) + c) * NN + n0 + 2 * n2]) = p;
    }
}

// ============================================================================
// Kernel 2: flash attention, split-K = 2, 128 queries / 8 warps per CTA.
// Memory tiles of 128 keys, processed as two 64-key online-softmax subtiles.
// Grid (32, 4, 2) = 256 CTAs, smem 72704 B -> 2 CTAs/SM, one full wave.
// ============================================================================
__global__ __launch_bounds__(256, 2) void attn_kernel()
{
    extern __shared__ char sm[];
    float (*Qs)[36]        = (float(*)[36])sm;                      // [128][36]
    float (*Ks)[128][36]   = (float(*)[128][36])(sm + 18432);       // [2][128][36]
    __nv_bfloat16 (*Vts)[32][136] =
        (__nv_bfloat16(*)[32][136])(sm + 55296);                    // [2][32][136]

    const int tid = threadIdx.x;
    const int w = tid >> 5, lane = tid & 31;
    const int g = lane >> 2, t = lane & 3;
    const int b = blockIdx.y;
    const int m0 = blockIdx.x * 128;
    const int kz = blockIdx.z;
    const int kbase = kz * 2048;
    const float LOG2E = 1.4426950408889634f;

    // Q tile (group 0): 128 rows x 8 float4 chunks = 1024 cp16
    const float* Qg = g_Q + ((size_t)b * NN + m0) * CLAT;
#pragma unroll
    for (int r = 0; r < 4; r++) {
        int idx = tid + r * 256;
        int row = idx >> 3, ch = idx & 7;
        cp16(sa(&Qs[row][ch * 4]), Qg + row * CLAT + ch * 4);
    }
    cpc();
    // prefetch K/V tile 0 (group 1)
    {
        const float* Kg = g_K + ((size_t)b * NN + kbase) * CLAT;
#pragma unroll
        for (int r = 0; r < 4; r++) {
            int idx = tid + r * 256;
            int row = idx >> 3, ch = idx & 7;
            cp16(sa(&Ks[0][row][ch * 4]), Kg + row * CLAT + ch * 4);
        }
        const __nv_bfloat16* Vg = g_Vt + (size_t)b * CLAT * NN + kbase;
#pragma unroll
        for (int r = 0; r < 2; r++) {
            int idx = tid + r * 256;
            int c = idx >> 4, ch = idx & 15;
            cp16(sa(&Vts[0][c][ch * 8]), Vg + (size_t)c * NN + ch * 8);
        }
    }
    cpc();
    cpw<1>();
    __syncthreads();

    uint32_t qa[4][4];
    const int r0 = w * 16 + g;
#pragma unroll
    for (int s = 0; s < 4; s++) {
        qa[s][0] = __float_as_uint(Qs[r0][8 * s + t]);
        qa[s][1] = __float_as_uint(Qs[r0 + 8][8 * s + t]);
        qa[s][2] = __float_as_uint(Qs[r0][8 * s + t + 4]);
        qa[s][3] = __float_as_uint(Qs[r0 + 8][8 * s + t + 4]);
    }

    float O[4][4];
#pragma unroll
    for (int o = 0; o < 4; o++)
#pragma unroll
        for (int j = 0; j < 4; j++) O[o][j] = 0.f;
    float mr0 = -1e30f, mr1 = -1e30f, lr0 = 0.f, lr1 = 0.f;

    const int NT = 2048 / 128;   // 16 memory tiles
    for (int kt = 0; kt < NT; kt++) {
        const int buf = kt & 1;
        __syncthreads();
        if (kt + 1 < NT) {
            const int k0 = kbase + (kt + 1) * 128;
            const int nb = (kt + 1) & 1;
            const float* Kg = g_K + ((size_t)b * NN + k0) * CLAT;
#pragma unroll
            for (int r = 0; r < 4; r++) {
                int idx = tid + r * 256;
                int row = idx >> 3, ch = idx & 7;
                cp16(sa(&Ks[nb][row][ch * 4]), Kg + row * CLAT + ch * 4);
            }
            const __nv_bfloat16* Vg = g_Vt + (size_t)b * CLAT * NN + k0;
#pragma unroll
            for (int r = 0; r < 2; r++) {
                int idx = tid + r * 256;
                int c = idx >> 4, ch = idx & 15;
                cp16(sa(&Vts[nb][c][ch * 8]), Vg + (size_t)c * NN + ch * 8);
            }
            cpc();
            cpw<1>();
        } else {
            cpw<0>();
        }
        __syncthreads();

        // two 64-key subtiles with independent online-softmax updates
#pragma unroll
        for (int half = 0; half < 2; half++) {
            const int koff = half * 64;
            float S[8][4];
#pragma unroll
            for (int j = 0; j < 8; j++)
#pragma unroll
                for (int q = 0; q < 4; q++) S[j][q] = 0.f;
#pragma unroll
            for (int s = 0; s < 4; s++) {
#pragma unroll
                for (int j = 0; j < 8; j++) {
                    uint32_t b0 = __float_as_uint(Ks[buf][koff + 8 * j + g][8 * s + t]);
                    uint32_t b1 = __float_as_uint(Ks[buf][koff + 8 * j + g][8 * s + t + 4]);
                    mma_tf32(S[j], qa[s], b0, b1);
                }
            }

            float mt0 = -1e30f, mt1 = -1e30f;
#pragma unroll
            for (int j = 0; j < 8; j++) {
                mt0 = fmaxf(mt0, fmaxf(S[j][0], S[j][1]));
                mt1 = fmaxf(mt1, fmaxf(S[j][2], S[j][3]));
            }
            mt0 = fmaxf(mt0, __shfl_xor_sync(0xffffffffu, mt0, 1));
            mt0 = fmaxf(mt0, __shfl_xor_sync(0xffffffffu, mt0, 2));
            mt1 = fmaxf(mt1, __shfl_xor_sync(0xffffffffu, mt1, 1));
            mt1 = fmaxf(mt1, __shfl_xor_sync(0xffffffffu, mt1, 2));
            float mn0 = fmaxf(mr0, mt0), mn1 = fmaxf(mr1, mt1);
            float sc0 = ex2f((mr0 - mn0) * LOG2E);
            float sc1 = ex2f((mr1 - mn1) * LOG2E);
            mr0 = mn0; mr1 = mn1;
            lr0 *= sc0; lr1 *= sc1;
#pragma unroll
            for (int o = 0; o < 4; o++) {
                O[o][0] *= sc0; O[o][1] *= sc0;
                O[o][2] *= sc1; O[o][3] *= sc1;
            }
            float ps0 = 0.f, ps1 = 0.f;
#pragma unroll
            for (int j = 0; j < 8; j++) {
                S[j][0] = ex2f((S[j][0] - mn0) * LOG2E);
                S[j][1] = ex2f((S[j][1] - mn0) * LOG2E);
                S[j][2] = ex2f((S[j][2] - mn1) * LOG2E);
                S[j][3] = ex2f((S[j][3] - mn1) * LOG2E);
                ps0 += S[j][0] + S[j][1];
                ps1 += S[j][2] + S[j][3];
            }
            ps0 += __shfl_xor_sync(0xffffffffu, ps0, 1);
            ps0 += __shfl_xor_sync(0xffffffffu, ps0, 2);
            ps1 += __shfl_xor_sync(0xffffffffu, ps1, 1);
            ps1 += __shfl_xor_sync(0xffffffffu, ps1, 2);
            lr0 += ps0; lr1 += ps1;

#pragma unroll
            for (int kk = 0; kk < 4; kk++) {
                uint32_t pa[4];
                pa[0] = pbf2(S[2 * kk][0], S[2 * kk][1]);
                pa[1] = pbf2(S[2 * kk][2], S[2 * kk][3]);
                pa[2] = pbf2(S[2 * kk + 1][0], S[2 * kk + 1][1]);
                pa[3] = pbf2(S[2 * kk + 1][2], S[2 * kk + 1][3]);
#pragma unroll
                for (int o = 0; o < 4; o++) {
                    uint32_t b0 = *reinterpret_cast<const uint32_t*>(
                        &Vts[buf][8 * o + g][koff + 16 * kk + 2 * t]);
                    uint32_t b1 = *reinterpret_cast<const uint32_t*>(
                        &Vts[buf][8 * o + g][koff + 16 * kk + 2 * t + 8]);
                    mma_bf16(O[o], pa, b0, b1);
                }
            }
        }
    }

    // epilogue: store UNNORMALIZED partials + (m, l)
    const int n_a = m0 + w * 16 + g;
    const int n_b = n_a + 8;
    float* P  = g_pO[kz] + ((size_t)b * NN + n_a) * CLAT;
    float* Pb = g_pO[kz] + ((size_t)b * NN + n_b) * CLAT;
#pragma unroll
    for (int o = 0; o < 4; o++) {
        int c = 8 * o + 2 * t;
        *reinterpret_cast<float2*>(&P[c])  = make_float2(O[o][0], O[o][1]);
        *reinterpret_cast<float2*>(&Pb[c]) = make_float2(O[o][2], O[o][3]);
    }
    if (t == 0) {
        g_pm[kz][b * NN + n_a] = mr0;
        g_pl[kz][b * NN + n_a] = lr0;
        g_pm[kz][b * NN + n_b] = mr1;
        g_pl[kz][b * NN + n_b] = lr1;
    }
}

// ============================================================================
// Kernel 3: fused split-K combine + out = gamma*ReLU(bn4(w_out@agg)) + x
// Grid (64 n-tiles, 4, 2 o-halves) = 512 CTAs, 256 threads.
// Thread: part = tid>>6 handles 32 outputs for n = n0 + (tid&63).
// ============================================================================
__global__ __launch_bounds__(256) void proj_kernel(
    const float* __restrict__ x, const float* __restrict__ w_out,
    const float* __restrict__ bn4s, const float* __restrict__ bn4b,
    const float* __restrict__ bn4m, const float* __restrict__ bn4v,
    const float* __restrict__ gamma_p, float* __restrict__ out)
{
    __shared__ __align__(16) float Wo[128 * 32];   // [o_local][c]
    __shared__ float As[64][33];                   // combined agg [n_local][c]
    __shared__ float sS[128], sB[128];
    __shared__ float sf0[64], sf1[64];

    const int tid = threadIdx.x;
    const int b = blockIdx.y;
    const int n0 = blockIdx.x * 64;
    const int oh = blockIdx.z * 128;
    const float LOG2E = 1.4426950408889634f;

    if (tid < 128) {
        int o = oh + tid;
        float inv = bn4s[o] * rsqrtf(bn4v[o] + 1e-5f);
        sS[tid] = inv;
        sB[tid] = bn4b[o] - bn4m[o] * inv;
    }
    // W half: 128 o x 32 c = 1024 float4
#pragma unroll
    for (int r = 0; r < 4; r++) {
        int idx = tid + r * 256;
        int o = idx >> 3, c4 = idx & 7;
        *reinterpret_cast<float4*>(&Wo[o * 32 + c4 * 4]) =
            *reinterpret_cast<const float4*>(&w_out[(oh + o) * CLAT + c4 * 4]);
    }
    // per-n split-K merge factors
    if (tid < 64) {
        int row = b * NN + n0 + tid;
        float m0 = g_pm[0][row], m1 = g_pm[1][row];
        float l0 = g_pl[0][row], l1 = g_pl[1][row];
        float m = fmaxf(m0, m1);
        float e0 = ex2f((m0 - m) * LOG2E);
        float e1 = ex2f((m1 - m) * LOG2E);
        float inv = 1.f / (l0 * e0 + l1 * e1);
        sf0[tid] = e0 * inv;
        sf1[tid] = e1 * inv;
    }
    __syncthreads();
    // combine pO partials into As: 64 n x 32 c = 512 float4
#pragma unroll
    for (int r = 0; r < 2; r++) {
        int idx = tid + r * 256;
        int n = idx >> 3, c4 = idx & 7;
        size_t base = ((size_t)(b * NN) + n0 + n) * CLAT + c4 * 4;
        float4 v0 = *reinterpret_cast<const float4*>(&g_pO[0][base]);
        float4 v1 = *reinterpret_cast<const float4*>(&g_pO[1][base]);
        float f0 = sf0[n], f1 = sf1[n];
        As[n][c4 * 4]     = v0.x * f0 + v1.x * f1;
        As[n][c4 * 4 + 1] = v0.y * f0 + v1.y * f1;
        As[n][c4 * 4 + 2] = v0.z * f0 + v1.z * f1;
        As[n][c4 * 4 + 3] = v0.w * f0 + v1.w * f1;
    }
    __syncthreads();

    const int nl = tid & 63, part = tid >> 6;
    const int n = n0 + nl;
    const int obase = part * 32;
    const float gamma = *gamma_p;

    float a[32];
#pragma unroll
    for (int c = 0; c < 32; c++) a[c] = As[nl][c];

    const float4* Wo4 = reinterpret_cast<const float4*>(Wo);
#pragma unroll 4
    for (int oo = 0; oo < 32; oo++) {
        int o = obase + oo;
        float d = 0.f;
#pragma unroll
        for (int c4 = 0; c4 < 8; c4++) {
            float4 wv = Wo4[o * 8 + c4];
            d += wv.x * a[c4 * 4] + wv.y * a[c4 * 4 + 1] +
                 wv.z * a[c4 * 4 + 2] + wv.w * a[c4 * 4 + 3];
        }
        float r = fmaxf(d * sS[o] + sB[o], 0.f);
        size_t gi = ((size_t)(b * CC + oh + o)) * NN + n;
        out[gi] = gamma * r + x[gi];
    }
}

// ============================================================================
extern "C" void kernel_launch(void* const* d_in, const int* in_sizes, int n_in,
                              void* d_out, int out_size)
{
    const float* x    = (const float*)d_in[0];
    const float* w1   = (const float*)d_in[1];
    const float* w2   = (const float*)d_in[2];
    const float* w3   = (const float*)d_in[3];
    const float* wout = (const float*)d_in[4];
    const float* bn1s = (const float*)d_in[5];
    const float* bn1b = (const float*)d_in[6];
    const float* bn1m = (const float*)d_in[7];
    const float* bn1v = (const float*)d_in[8];
    const float* bn2s = (const float*)d_in[9];
    const float* bn2b = (const float*)d_in[10];
    const float* bn2m = (const float*)d_in[11];
    const float* bn2v = (const float*)d_in[12];
    const float* bn3s = (const float*)d_in[13];
    const float* bn3b = (const float*)d_in[14];
    const float* bn3m = (const float*)d_in[15];
    const float* bn3v = (const float*)d_in[16];
    const float* bn4s = (const float*)d_in[17];
    const float* bn4b = (const float*)d_in[18];
    const float* bn4m = (const float*)d_in[19];
    const float* bn4v = (const float*)d_in[20];
    const float* gam  = (const float*)d_in[21];
    float* out = (float*)d_out;

    const int QKV_SMEM = 174336;
    const int ATTN_SMEM = 72704;
    cudaFuncSetAttribute(qkv_mma, cudaFuncAttributeMaxDynamicSharedMemorySize,
                         QKV_SMEM);
    cudaFuncSetAttribute(attn_kernel, cudaFuncAttributeMaxDynamicSharedMemorySize,
                         ATTN_SMEM);

    qkv_mma<<<dim3(NN / 64, BB), 256, QKV_SMEM>>>(x, w1, w2, w3,
                                                  bn1s, bn1b, bn1m, bn1v,
                                                  bn2s, bn2b, bn2m, bn2v,
                                                  bn3s, bn3b, bn3m, bn3v);
    attn_kernel<<<dim3(NN / 128, BB, 2), 256, ATTN_SMEM>>>();
    proj_kernel<<<dim3(NN / 64, BB, 2), 256>>>(x, wout, bn4s, bn4b, bn4m, bn4v,
                                               gam, out);
}

// round 6
// speedup vs baseline: 1.5289x; 1.1386x over previous
#include <cuda_runtime.h>
#include <cuda_bf16.h>
#include <cstdint>

// Problem constants
#define BB 4
#define CC 256
#define CLAT 32
#define NN 4096
#define SPLITS 4

// Scratch (device globals -- no allocation allowed)
__device__ float g_Q[BB * NN * CLAT];          // [b][n][32] tf32-rounded
// K packed in mma-B-fragment order, 64-key blocks of 2048 floats
__device__ float g_Kp[BB * NN * CLAT];
// V packed in mma-B-fragment order (bf16x2 units), 64-key blocks of 1024 u32
__device__ uint32_t g_Vp[BB * NN * CLAT / 2];
// split-K attention partials
__device__ float g_pO[SPLITS][BB * NN * CLAT];
__device__ float g_pm[SPLITS][BB * NN];
__device__ float g_pl[SPLITS][BB * NN];

// ---------------- helpers ----------------
__device__ __forceinline__ uint32_t sa(const void* p) {
    return (uint32_t)__cvta_generic_to_shared(p);
}
__device__ __forceinline__ void cp16(uint32_t s, const void* g) {
    asm volatile("cp.async.cg.shared.global [%0],[%1],16;\n" :: "r"(s), "l"(g));
}
__device__ __forceinline__ void cpc() { asm volatile("cp.async.commit_group;\n"); }
template <int W> __device__ __forceinline__ void cpw() {
    asm volatile("cp.async.wait_group %0;\n" :: "n"(W));
}
__device__ __forceinline__ float ex2f(float x) {
    float y; asm("ex2.approx.f32 %0,%1;" : "=f"(y) : "f"(x)); return y;
}
__device__ __forceinline__ float tf32r(float x) {
    uint32_t u; asm("cvt.rna.tf32.f32 %0,%1;" : "=r"(u) : "f"(x));
    return __uint_as_float(u);
}
__device__ __forceinline__ uint32_t pbf2(float lo, float hi) {
    uint32_t r; asm("cvt.rn.bf16x2.f32 %0,%1,%2;" : "=r"(r) : "f"(hi), "f"(lo));
    return r;
}
__device__ __forceinline__ void mma_tf32(float d[4], const uint32_t a[4],
                                         uint32_t b0, uint32_t b1) {
    asm volatile(
        "mma.sync.aligned.m16n8k8.row.col.f32.tf32.tf32.f32 "
        "{%0,%1,%2,%3},{%4,%5,%6,%7},{%8,%9},{%0,%1,%2,%3};\n"
        : "+f"(d[0]), "+f"(d[1]), "+f"(d[2]), "+f"(d[3])
        : "r"(a[0]), "r"(a[1]), "r"(a[2]), "r"(a[3]), "r"(b0), "r"(b1));
}
__device__ __forceinline__ void mma_bf16(float d[4], const uint32_t a[4],
                                         uint32_t b0, uint32_t b1) {
    asm volatile(
        "mma.sync.aligned.m16n8k16.row.col.f32.bf16.bf16.f32 "
        "{%0,%1,%2,%3},{%4,%5,%6,%7},{%8,%9},{%0,%1,%2,%3};\n"
        : "+f"(d[0]), "+f"(d[1]), "+f"(d[2]), "+f"(d[3])
        : "r"(a[0]), "r"(a[1]), "r"(a[2]), "r"(a[3]), "r"(b0), "r"(b1));
}

// K packed offset within a 64-key block (floats).
__device__ __forceinline__ int kpoff(int np, int c) {
    return (np >> 3) * 256 + ((c >> 4) & 1) * 128 + (np & 7) * 16 +
           (c & 3) * 4 + ((c >> 3) & 1) * 2 + ((c >> 2) & 1);
}

// ============================================================================
// Kernel 1: QKV projection via tf32 mma.sync.
// ============================================================================
__global__ __launch_bounds__(256, 1) void qkv_mma(
    const float* __restrict__ x,
    const float* __restrict__ w1, const float* __restrict__ w2,
    const float* __restrict__ w3,
    const float* __restrict__ bn1s, const float* __restrict__ bn1b,
    const float* __restrict__ bn1m, const float* __restrict__ bn1v,
    const float* __restrict__ bn2s, const float* __restrict__ bn2b,
    const float* __restrict__ bn2m, const float* __restrict__ bn2v,
    const float* __restrict__ bn3s, const float* __restrict__ bn3b,
    const float* __restrict__ bn3m, const float* __restrict__ bn3v)
{
    extern __shared__ char sm[];
    float* Ws  = (float*)sm;                         // [96][260]
    float* Xs  = (float*)(sm + 99840);               // [4][64][72]
    float* sSc = (float*)(sm + 173568);              // [96]
    float* sBi = (float*)(sm + 173952);              // [96]
    __nv_bfloat16* Vst = (__nv_bfloat16*)(sm + 99840); // reuse Xs: [32][72]

    const int tid = threadIdx.x;
    const int b = blockIdx.y;
    const int n0 = blockIdx.x * 64;

    if (tid < 96) {
        int grp = tid >> 5, o = tid & 31;
        const float *s_, *b_, *m_, *v_;
        if (grp == 0)      { s_ = bn1s; b_ = bn1b; m_ = bn1m; v_ = bn1v; }
        else if (grp == 1) { s_ = bn2s; b_ = bn2b; m_ = bn2m; v_ = bn2v; }
        else               { s_ = bn3s; b_ = bn3b; m_ = bn3m; v_ = bn3v; }
        float inv = s_[o] * rsqrtf(v_[o] + 1e-5f);
        sSc[tid] = inv;
        sBi[tid] = b_[o] - m_[o] * inv;
    }

#pragma unroll
    for (int r = 0; r < 24; r++) {
        int idx = tid + r * 256;
        int o = idx >> 6, c4 = idx & 63;
        const float* w = (o < 32) ? w1 : (o < 64) ? w2 : w3;
        float4 v = *reinterpret_cast<const float4*>(&w[(o & 31) * CC + c4 * 4]);
        float4 t;
        t.x = tf32r(v.x); t.y = tf32r(v.y); t.z = tf32r(v.z); t.w = tf32r(v.w);
        *reinterpret_cast<float4*>(&Ws[o * 260 + c4 * 4]) = t;
    }

#pragma unroll
    for (int ch = 0; ch < 4; ch++) {
#pragma unroll
        for (int r = 0; r < 4; r++) {
            int idx = tid + r * 256;
            int cc = idx >> 4, c4 = idx & 15;
            cp16(sa(&Xs[ch * 4608 + cc * 72 + c4 * 4]),
                 &x[(size_t)(b * CC + ch * 64 + cc) * NN + n0 + c4 * 4]);
        }
        cpc();
    }

    const int w = tid >> 5, lane = tid & 31;
    const int g = lane >> 2, t = lane & 3;
    const int rows16 = (w & 3) * 16;
    const int jbase = (w >> 2) * 6;

    float C[6][4];
#pragma unroll
    for (int j = 0; j < 6; j++)
#pragma unroll
        for (int q = 0; q < 4; q++) C[j][q] = 0.f;

#pragma unroll
    for (int ch = 0; ch < 4; ch++) {
        if (ch == 0) cpw<3>();
        else if (ch == 1) cpw<2>();
        else if (ch == 2) cpw<1>();
        else cpw<0>();
        __syncthreads();
        const float* Xc = &Xs[ch * 4608];
#pragma unroll
        for (int s = 0; s < 8; s++) {
            uint32_t a[4];
            int cl = s * 8 + t;
            a[0] = __float_as_uint(tf32r(Xc[cl * 72 + rows16 + g]));
            a[1] = __float_as_uint(tf32r(Xc[cl * 72 + rows16 + g + 8]));
            a[2] = __float_as_uint(tf32r(Xc[(cl + 4) * 72 + rows16 + g]));
            a[3] = __float_as_uint(tf32r(Xc[(cl + 4) * 72 + rows16 + g + 8]));
            int cg = ch * 64 + s * 8;
#pragma unroll
            for (int jj = 0; jj < 6; jj++) {
                int o = (jbase + jj) * 8 + g;
                uint32_t b0 = __float_as_uint(Ws[o * 260 + cg + t]);
                uint32_t b1 = __float_as_uint(Ws[o * 260 + cg + t + 4]);
                mma_tf32(C[jj], a, b0, b1);
            }
        }
    }
    __syncthreads();

    const int n_a = n0 + rows16 + g;
    const int n_b = n_a + 8;
    const int np_a = rows16 + g;          // within 64-tile
    float* Kt = g_Kp + ((size_t)(b * 64) + (n0 >> 6)) * 2048;
#pragma unroll
    for (int jj = 0; jj < 6; jj++) {
        int ob = (jbase + jj) * 8 + 2 * t;
        float sc0 = sSc[ob], bi0 = sBi[ob];
        float sc1 = sSc[ob + 1], bi1 = sBi[ob + 1];
        float v00 = fmaxf(C[jj][0] * sc0 + bi0, 0.f);
        float v01 = fmaxf(C[jj][1] * sc1 + bi1, 0.f);
        float v10 = fmaxf(C[jj][2] * sc0 + bi0, 0.f);
        float v11 = fmaxf(C[jj][3] * sc1 + bi1, 0.f);
        if (ob < 32) {
            *reinterpret_cast<float2*>(&g_Q[((size_t)(b * NN) + n_a) * CLAT + ob]) =
                make_float2(tf32r(v00), tf32r(v01));
            *reinterpret_cast<float2*>(&g_Q[((size_t)(b * NN) + n_b) * CLAT + ob]) =
                make_float2(tf32r(v10), tf32r(v11));
        } else if (ob < 64) {
            int c = ob & 31;
            Kt[kpoff(np_a, c)]         = tf32r(v00);
            Kt[kpoff(np_a, c + 1)]     = tf32r(v01);
            Kt[kpoff(np_a + 8, c)]     = tf32r(v10);
            Kt[kpoff(np_a + 8, c + 1)] = tf32r(v11);
        } else {
            int c = ob - 64;
            int nl = rows16 + g;
            Vst[c * 72 + nl]           = __float2bfloat16(v00);
            Vst[(c + 1) * 72 + nl]     = __float2bfloat16(v01);
            Vst[c * 72 + nl + 8]       = __float2bfloat16(v10);
            Vst[(c + 1) * 72 + nl + 8] = __float2bfloat16(v11);
        }
    }
    __syncthreads();
    // V flush: packed layout.
    uint32_t* Vt = g_Vp + ((size_t)(b * 64) + (n0 >> 6)) * 1024;
#pragma unroll
    for (int r = 0; r < 4; r++) {
        int p = tid + r * 256;
        int e = p & 3;
        int p16 = p >> 2;
        int kkl = p16 >> 6;
        int u = p16 & 63;
        int opair = u >> 5;
        int u5 = u & 31;
        int gg = (u5 >> 3) * 2 + ((u5 >> 2) & 1);
        int tt = u5 & 3;
        int o = opair * 2 + (e >> 1);
        int h = e & 1;
        int c = 8 * o + gg;
        int n2loc = kkl * 8 + 4 * h + tt;
        __nv_bfloat162 pr;
        pr.x = Vst[c * 72 + 2 * n2loc];
        pr.y = Vst[c * 72 + 2 * n2loc + 1];
        Vt[p] = *reinterpret_cast<uint32_t*>(&pr);
    }
}

// ============================================================================
// Kernel 2: flash attention, split-K = 4.
// CTA: 64 queries (4 warps x 16 rows) x 1024 keys (8 tiles of 128).
// K/V read from fragment-packed gmem -> LDS.128 fragment loads.
// smem: Qs 9216 + Kp 2x16384 + Vp 2x8192 = 58368 B -> 3 CTAs/SM.
// ============================================================================
__global__ __launch_bounds__(128) void attn_kernel()
{
    extern __shared__ char sm[];
    float (*Qs)[36] = (float(*)[36])sm;               // [64][36]   : 9216 B
    float* Ksm      = (float*)(sm + 9216);            // [2][4096]  : 32768 B
    uint32_t* Vsm   = (uint32_t*)(sm + 41984);        // [2][2048]  : 16384 B

    const int tid = threadIdx.x;
    const int w = tid >> 5, lane = tid & 31;
    const int g = lane >> 2, t = lane & 3;
    const int b = blockIdx.y;
    const int m0 = blockIdx.x * 64;
    const int kz = blockIdx.z;
    const float LOG2E = 1.4426950408889634f;
    const int NT = (NN / SPLITS) / 128;               // 8 tiles
    const int kt2base = kz * NT;                      // global 128-tile index base

    // Q tile (group 0)
    const float* Qg = g_Q + ((size_t)b * NN + m0) * CLAT;
#pragma unroll
    for (int r = 0; r < 4; r++) {
        int idx = tid + r * 128;
        int row = idx >> 3, ch = idx & 7;
        cp16(sa(&Qs[row][ch * 4]), Qg + row * CLAT + ch * 4);
    }
    cpc();
    // prefetch K/V tile 0 (group 1): linear 16KB + 8KB copies
    {
        const float* Kg = g_Kp + ((size_t)(b * 64) + kt2base * 2) * 2048;
#pragma unroll
        for (int r = 0; r < 8; r++) {
            int idx = tid + r * 128;
            cp16(sa(Ksm + idx * 4), Kg + idx * 4);
        }
        const uint32_t* Vg = g_Vp + ((size_t)(b * 64) + kt2base * 2) * 1024;
#pragma unroll
        for (int r = 0; r < 4; r++) {
            int idx = tid + r * 128;
            cp16(sa(Vsm + idx * 4), Vg + idx * 4);
        }
    }
    cpc();
    cpw<1>();
    __syncthreads();

    uint32_t qa[4][4];
    const int r0 = w * 16 + g;
#pragma unroll
    for (int s = 0; s < 4; s++) {
        qa[s][0] = __float_as_uint(Qs[r0][8 * s + t]);
        qa[s][1] = __float_as_uint(Qs[r0 + 8][8 * s + t]);
        qa[s][2] = __float_as_uint(Qs[r0][8 * s + t + 4]);
        qa[s][3] = __float_as_uint(Qs[r0 + 8][8 * s + t + 4]);
    }

    float O[4][4];
#pragma unroll
    for (int o = 0; o < 4; o++)
#pragma unroll
        for (int j = 0; j < 4; j++) O[o][j] = 0.f;
    float mr0 = -1e30f, mr1 = -1e30f, lr0 = 0.f, lr1 = 0.f;

    for (int kt = 0; kt < NT; kt++) {
        const int buf = kt & 1;
        __syncthreads();
        if (kt + 1 < NT) {
            const int nb = (kt + 1) & 1;
            const float* Kg = g_Kp + ((size_t)(b * 64) + (kt2base + kt + 1) * 2) * 2048;
#pragma unroll
            for (int r = 0; r < 8; r++) {
                int idx = tid + r * 128;
                cp16(sa(Ksm + nb * 4096 + idx * 4), Kg + idx * 4);
            }
            const uint32_t* Vg = g_Vp + ((size_t)(b * 64) + (kt2base + kt + 1) * 2) * 1024;
#pragma unroll
            for (int r = 0; r < 4; r++) {
                int idx = tid + r * 128;
                cp16(sa(Vsm + nb * 2048 + idx * 4), Vg + idx * 4);
            }
            cpc();
            cpw<1>();
        } else {
            cpw<0>();
        }
        __syncthreads();

        // S = Q K^T : 16 j-tiles of 8 keys, K fragments via LDS.128
        float S[16][4];
#pragma unroll
        for (int j = 0; j < 16; j++)
#pragma unroll
            for (int q = 0; q < 4; q++) S[j][q] = 0.f;

        const float* Kb = Ksm + buf * 4096 + g * 16 + t * 4;
#pragma unroll
        for (int j = 0; j < 16; j++) {
            const float* kp = Kb + (j >> 3) * 2048 + (j & 7) * 256;
            float4 f0 = *reinterpret_cast<const float4*>(kp);
            float4 f1 = *reinterpret_cast<const float4*>(kp + 128);
            mma_tf32(S[j], qa[0], __float_as_uint(f0.x), __float_as_uint(f0.y));
            mma_tf32(S[j], qa[1], __float_as_uint(f0.z), __float_as_uint(f0.w));
            mma_tf32(S[j], qa[2], __float_as_uint(f1.x), __float_as_uint(f1.y));
            mma_tf32(S[j], qa[3], __float_as_uint(f1.z), __float_as_uint(f1.w));
        }

        // online softmax
        float mt0 = -1e30f, mt1 = -1e30f;
#pragma unroll
        for (int j = 0; j < 16; j++) {
            mt0 = fmaxf(mt0, fmaxf(S[j][0], S[j][1]));
            mt1 = fmaxf(mt1, fmaxf(S[j][2], S[j][3]));
        }
        mt0 = fmaxf(mt0, __shfl_xor_sync(0xffffffffu, mt0, 1));
        mt0 = fmaxf(mt0, __shfl_xor_sync(0xffffffffu, mt0, 2));
        mt1 = fmaxf(mt1, __shfl_xor_sync(0xffffffffu, mt1, 1));
        mt1 = fmaxf(mt1, __shfl_xor_sync(0xffffffffu, mt1, 2));
        float mn0 = fmaxf(mr0, mt0), mn1 = fmaxf(mr1, mt1);
        float sc0 = ex2f((mr0 - mn0) * LOG2E);
        float sc1 = ex2f((mr1 - mn1) * LOG2E);
        mr0 = mn0; mr1 = mn1;
        lr0 *= sc0; lr1 *= sc1;
#pragma unroll
        for (int o = 0; o < 4; o++) {
            O[o][0] *= sc0; O[o][1] *= sc0;
            O[o][2] *= sc1; O[o][3] *= sc1;
        }
        float ps0 = 0.f, ps1 = 0.f;
#pragma unroll
        for (int j = 0; j < 16; j++) {
            S[j][0] = ex2f((S[j][0] - mn0) * LOG2E);
            S[j][1] = ex2f((S[j][1] - mn0) * LOG2E);
            S[j][2] = ex2f((S[j][2] - mn1) * LOG2E);
            S[j][3] = ex2f((S[j][3] - mn1) * LOG2E);
            ps0 += S[j][0] + S[j][1];
            ps1 += S[j][2] + S[j][3];
        }
        ps0 += __shfl_xor_sync(0xffffffffu, ps0, 1);
        ps0 += __shfl_xor_sync(0xffffffffu, ps0, 2);
        ps1 += __shfl_xor_sync(0xffffffffu, ps1, 1);
        ps1 += __shfl_xor_sync(0xffffffffu, ps1, 2);
        lr0 += ps0; lr1 += ps1;

        // O += P V : V fragments via LDS.128
        const uint32_t* Vb = Vsm + buf * 2048 + (g >> 1) * 32 + ((g & 1) * 4 + t) * 4;
#pragma unroll
        for (int kk = 0; kk < 8; kk++) {
            uint32_t pa[4];
            pa[0] = pbf2(S[2 * kk][0], S[2 * kk][1]);
            pa[1] = pbf2(S[2 * kk][2], S[2 * kk][3]);
            pa[2] = pbf2(S[2 * kk + 1][0], S[2 * kk + 1][1]);
            pa[3] = pbf2(S[2 * kk + 1][2], S[2 * kk + 1][3]);
            const uint32_t* vp = Vb + (kk >> 2) * 1024 + (kk & 3) * 256;
            uint4 va = *reinterpret_cast<const uint4*>(vp);
            uint4 vb = *reinterpret_cast<const uint4*>(vp + 128);
            mma_bf16(O[0], pa, va.x, va.y);
            mma_bf16(O[1], pa, va.z, va.w);
            mma_bf16(O[2], pa, vb.x, vb.y);
            mma_bf16(O[3], pa, vb.z, vb.w);
        }
    }

    // epilogue: store UNNORMALIZED partials + (m, l)
    const int n_a = m0 + w * 16 + g;
    const int n_b = n_a + 8;
    float* P  = g_pO[kz] + ((size_t)b * NN + n_a) * CLAT;
    float* Pb = g_pO[kz] + ((size_t)b * NN + n_b) * CLAT;
#pragma unroll
    for (int o = 0; o < 4; o++) {
        int c = 8 * o + 2 * t;
        *reinterpret_cast<float2*>(&P[c])  = make_float2(O[o][0], O[o][1]);
        *reinterpret_cast<float2*>(&Pb[c]) = make_float2(O[o][2], O[o][3]);
    }
    if (t == 0) {
        g_pm[kz][b * NN + n_a] = mr0;
        g_pl[kz][b * NN + n_a] = lr0;
        g_pm[kz][b * NN + n_b] = mr1;
        g_pl[kz][b * NN + n_b] = lr1;
    }
}

// ============================================================================
// Kernel 3: fused split-K combine + out = gamma*ReLU(bn4(w_out@agg)) + x
// ============================================================================
__global__ __launch_bounds__(256) void proj_kernel(
    const float* __restrict__ x, const float* __restrict__ w_out,
    const float* __restrict__ bn4s, const float* __restrict__ bn4b,
    const float* __restrict__ bn4m, const float* __restrict__ bn4v,
    const float* __restrict__ gamma_p, float* __restrict__ out)
{
    __shared__ __align__(16) float Wo[128 * 32];
    __shared__ float As[64][33];
    __shared__ float sS[128], sB[128];
    __shared__ float sf[SPLITS][64];

    const int tid = threadIdx.x;
    const int b = blockIdx.y;
    const int n0 = blockIdx.x * 64;
    const int oh = blockIdx.z * 128;
    const float LOG2E = 1.4426950408889634f;

    if (tid < 128) {
        int o = oh + tid;
        float inv = bn4s[o] * rsqrtf(bn4v[o] + 1e-5f);
        sS[tid] = inv;
        sB[tid] = bn4b[o] - bn4m[o] * inv;
    }
#pragma unroll
    for (int r = 0; r < 4; r++) {
        int idx = tid + r * 256;
        int o = idx >> 3, c4 = idx & 7;
        *reinterpret_cast<float4*>(&Wo[o * 32 + c4 * 4]) =
            *reinterpret_cast<const float4*>(&w_out[(oh + o) * CLAT + c4 * 4]);
    }
    if (tid < 64) {
        int row = b * NN + n0 + tid;
        float m0 = g_pm[0][row], m1 = g_pm[1][row];
        float m2 = g_pm[2][row], m3 = g_pm[3][row];
        float m = fmaxf(fmaxf(m0, m1), fmaxf(m2, m3));
        float e0 = ex2f((m0 - m) * LOG2E);
        float e1 = ex2f((m1 - m) * LOG2E);
        float e2 = ex2f((m2 - m) * LOG2E);
        float e3 = ex2f((m3 - m) * LOG2E);
        float inv = 1.f / (g_pl[0][row] * e0 + g_pl[1][row] * e1 +
                           g_pl[2][row] * e2 + g_pl[3][row] * e3);
        sf[0][tid] = e0 * inv;
        sf[1][tid] = e1 * inv;
        sf[2][tid] = e2 * inv;
        sf[3][tid] = e3 * inv;
    }
    __syncthreads();
#pragma unroll
    for (int r = 0; r < 2; r++) {
        int idx = tid + r * 256;
        int n = idx >> 3, c4 = idx & 7;
        size_t base = ((size_t)(b * NN) + n0 + n) * CLAT + c4 * 4;
        float4 acc = make_float4(0.f, 0.f, 0.f, 0.f);
#pragma unroll
        for (int z = 0; z < SPLITS; z++) {
            float4 v = *reinterpret_cast<const float4*>(&g_pO[z][base]);
            float f = sf[z][n];
            acc.x += v.x * f; acc.y += v.y * f;
            acc.z += v.z * f; acc.w += v.w * f;
        }
        As[n][c4 * 4]     = acc.x;
        As[n][c4 * 4 + 1] = acc.y;
        As[n][c4 * 4 + 2] = acc.z;
        As[n][c4 * 4 + 3] = acc.w;
    }
    __syncthreads();

    const int nl = tid & 63, part = tid >> 6;
    const int n = n0 + nl;
    const int obase = part * 32;
    const float gamma = *gamma_p;

    float a[32];
#pragma unroll
    for (int c = 0; c < 32; c++) a[c] = As[nl][c];

    const float4* Wo4 = reinterpret_cast<const float4*>(Wo);
#pragma unroll 4
    for (int oo = 0; oo < 32; oo++) {
        int o = obase + oo;
        float d = 0.f;
#pragma unroll
        for (int c4 = 0; c4 < 8; c4++) {
            float4 wv = Wo4[o * 8 + c4];
            d += wv.x * a[c4 * 4] + wv.y * a[c4 * 4 + 1] +
                 wv.z * a[c4 * 4 + 2] + wv.w * a[c4 * 4 + 3];
        }
        float r = fmaxf(d * sS[o] + sB[o], 0.f);
        size_t gi = ((size_t)(b * CC + oh + o)) * NN + n;
        out[gi] = gamma * r + x[gi];
    }
}

// ============================================================================
extern "C" void kernel_launch(void* const* d_in, const int* in_sizes, int n_in,
                              void* d_out, int out_size)
{
    const float* x    = (const float*)d_in[0];
    const float* w1   = (const float*)d_in[1];
    const float* w2   = (const float*)d_in[2];
    const float* w3   = (const float*)d_in[3];
    const float* wout = (const float*)d_in[4];
    const float* bn1s = (const float*)d_in[5];
    const float* bn1b = (const float*)d_in[6];
    const float* bn1m = (const float*)d_in[7];
    const float* bn1v = (const float*)d_in[8];
    const float* bn2s = (const float*)d_in[9];
    const float* bn2b = (const float*)d_in[10];
    const float* bn2m = (const float*)d_in[11];
    const float* bn2v = (const float*)d_in[12];
    const float* bn3s = (const float*)d_in[13];
    const float* bn3b = (const float*)d_in[14];
    const float* bn3m = (const float*)d_in[15];
    const float* bn3v = (const float*)d_in[16];
    const float* bn4s = (const float*)d_in[17];
    const float* bn4b = (const float*)d_in[18];
    const float* bn4m = (const float*)d_in[19];
    const float* bn4v = (const float*)d_in[20];
    const float* gam  = (const float*)d_in[21];
    float* out = (float*)d_out;

    const int QKV_SMEM = 174336;
    const int ATTN_SMEM = 58368;
    cudaFuncSetAttribute(qkv_mma, cudaFuncAttributeMaxDynamicSharedMemorySize,
                         QKV_SMEM);
    cudaFuncSetAttribute(attn_kernel, cudaFuncAttributeMaxDynamicSharedMemorySize,
                         ATTN_SMEM);

    qkv_mma<<<dim3(NN / 64, BB), 256, QKV_SMEM>>>(x, w1, w2, w3,
                                                  bn1s, bn1b, bn1m, bn1v,
                                                  bn2s, bn2b, bn2m, bn2v,
                                                  bn3s, bn3b, bn3m, bn3v);
    attn_kernel<<<dim3(NN / 64, BB, SPLITS), 128, ATTN_SMEM>>>();
    proj_kernel<<<dim3(NN / 64, BB, 2), 256>>>(x, wout, bn4s, bn4b, bn4m, bn4v,
                                               gam, out);
}